// round 1
// baseline (speedup 1.0000x reference)
#include <cuda_runtime.h>
#include <math.h>

#define NTOK 8192
#define H 2048
#define T 256
#define E 16
#define R 512

// ---- scratch (static __device__, no allocation) ----
__device__ float g_cnorm[E * T];      // normalized centroids
__device__ int   g_counts[E];         // tokens per expert
__device__ int   g_tok[E * NTOK];     // per-expert token index lists
__device__ float g_pstar[NTOK];       // chosen expert prob per token
__device__ float g_h1[NTOK * R];      // gelu(x @ Wd_e) stored at token's own row

__device__ __forceinline__ float gelu_f(float v) {
    return 0.5f * v * (1.0f + erff(v * 0.70710678118654752440f));
}

// ---------------------------------------------------------------------------
// K0: zero counters + normalize centroids
// ---------------------------------------------------------------------------
__global__ void prep_kernel(const float* __restrict__ centroids) {
    __shared__ float inv[E];
    int t = threadIdx.x;
    if (t < E) {
        g_counts[t] = 0;
        float ss = 0.f;
        const float* c = centroids + t * T;
        for (int j = 0; j < T; j++) { float v = c[j]; ss += v * v; }
        inv[t] = 1.0f / fmaxf(sqrtf(ss), 1e-8f);
    }
    __syncthreads();
    for (int idx = t; idx < E * T; idx += blockDim.x)
        g_cnorm[idx] = centroids[idx] * inv[idx / T];
}

// ---------------------------------------------------------------------------
// K1: fused router. One block = 16 tokens, 256 threads.
//   distilled = gelu(x @ Wdist + b); d = l2norm(distilled);
//   dist_e = sqrt(max(2 - 2 d.c_e, 0)); probs = softmax(-dist);
//   top-2 (jax tie rule: higher prob first, tie -> lower index);
//   e* = max(top2 indices), p* = probs[e*]; scatter into expert lists.
// ---------------------------------------------------------------------------
__global__ __launch_bounds__(256) void router_kernel(
    const float* __restrict__ premise,
    const float* __restrict__ Wdist,
    const float* __restrict__ bdist) {
    __shared__ float xs[16][128];
    __shared__ float ds[16][T];
    int t = threadIdx.x;
    int tok0 = blockIdx.x * 16;

    float acc[16];
#pragma unroll
    for (int m = 0; m < 16; m++) acc[m] = 0.f;

    for (int k0 = 0; k0 < H; k0 += 128) {
#pragma unroll
        for (int i = 0; i < 8; i++) {
            int idx = t + i * 256;
            xs[idx >> 7][idx & 127] =
                premise[(size_t)(tok0 + (idx >> 7)) * H + k0 + (idx & 127)];
        }
        __syncthreads();
#pragma unroll 4
        for (int kk = 0; kk < 128; kk++) {
            float w = Wdist[(size_t)(k0 + kk) * T + t];
#pragma unroll
            for (int m = 0; m < 16; m++) acc[m] = fmaf(xs[m][kk], w, acc[m]);
        }
        __syncthreads();
    }

    float b = bdist[t];
#pragma unroll
    for (int m = 0; m < 16; m++) ds[m][t] = gelu_f(acc[m] + b);
    __syncthreads();

    int warp = t >> 5, lane = t & 31;
#pragma unroll
    for (int mi = 0; mi < 2; mi++) {
        int m = warp * 2 + mi;
        // sum of squares over the 256-dim distilled vector
        float ss = 0.f;
#pragma unroll
        for (int j = lane; j < T; j += 32) { float v = ds[m][j]; ss += v * v; }
#pragma unroll
        for (int o = 16; o; o >>= 1) ss += __shfl_xor_sync(0xffffffffu, ss, o);
        float inv = 1.0f / fmaxf(sqrtf(ss), 1e-8f);

        float logit = -1e30f;
        if (lane < E) {
            float dot = 0.f;
            const float* cn = &g_cnorm[lane * T];
            for (int j = 0; j < T; j++) dot = fmaf(ds[m][j], cn[j], dot);
            dot *= inv;
            float dist = sqrtf(fmaxf(2.f - 2.f * dot, 0.f));
            logit = -dist;
        }
        // softmax over 16 lanes (others contribute 0)
        float mx = logit;
#pragma unroll
        for (int o = 16; o; o >>= 1) mx = fmaxf(mx, __shfl_xor_sync(0xffffffffu, mx, o));
        float ex = (lane < E) ? expf(logit - mx) : 0.f;
        float sum = ex;
#pragma unroll
        for (int o = 16; o; o >>= 1) sum += __shfl_xor_sync(0xffffffffu, sum, o);
        float prob = ex / sum;

        // top-1 (prob desc, index asc on tie)
        float p1 = prob; int i1 = lane;
#pragma unroll
        for (int o = 16; o; o >>= 1) {
            float po = __shfl_xor_sync(0xffffffffu, p1, o);
            int   io = __shfl_xor_sync(0xffffffffu, i1, o);
            if (po > p1 || (po == p1 && io < i1)) { p1 = po; i1 = io; }
        }
        // top-2: exclude i1
        float p2 = (lane == i1) ? -1.f : prob; int i2 = lane;
#pragma unroll
        for (int o = 16; o; o >>= 1) {
            float po = __shfl_xor_sync(0xffffffffu, p2, o);
            int   io = __shfl_xor_sync(0xffffffffu, i2, o);
            if (po > p2 || (po == p2 && io < i2)) { p2 = po; i2 = io; }
        }
        int e_star = max(i1, i2);
        float p_star = (e_star == i1) ? p1 : p2;
        if (lane == 0) {
            int tok = tok0 + m;
            g_pstar[tok] = p_star;
            int pos = atomicAdd(&g_counts[e_star], 1);
            g_tok[e_star * NTOK + pos] = tok;
        }
    }
}

// ---------------------------------------------------------------------------
// K2: gathered GEMM  h1 = gelu(X_e @ Wd[e])   [cnt_e, R]
// Tile 64x64, K-tile 16, 256 threads, 4x4 microtile.
// ---------------------------------------------------------------------------
__global__ __launch_bounds__(256) void expert_gemm1(
    const float* __restrict__ premise,
    const float* __restrict__ Wd) {
    int e = blockIdx.z;
    int cnt = g_counts[e];
    int m0 = blockIdx.y * 64;
    if (m0 >= cnt) return;
    int n0 = blockIdx.x * 64;

    __shared__ float As[16][64];
    __shared__ float Bs[16][64];
    __shared__ int toks[64];

    int tid = threadIdx.x;
    if (tid < 64) toks[tid] = g_tok[e * NTOK + min(m0 + tid, cnt - 1)];
    __syncthreads();

    int tx = tid & 15, ty = tid >> 4;
    int arow = tid >> 2;
    int akk = (tid & 3) * 4;
    int bkk = (tid * 4) >> 6;
    int bnn = (tid * 4) & 63;
    const float* Wde = Wd + (size_t)e * H * R;
    size_t arow_base = (size_t)toks[arow] * H;

    float acc[4][4];
#pragma unroll
    for (int i = 0; i < 4; i++)
#pragma unroll
        for (int j = 0; j < 4; j++) acc[i][j] = 0.f;

    for (int k0 = 0; k0 < H; k0 += 16) {
        float4 av = *(const float4*)&premise[arow_base + k0 + akk];
        float4 bv = *(const float4*)&Wde[(size_t)(k0 + bkk) * R + n0 + bnn];
        __syncthreads();
        As[akk + 0][arow] = av.x; As[akk + 1][arow] = av.y;
        As[akk + 2][arow] = av.z; As[akk + 3][arow] = av.w;
        *(float4*)&Bs[bkk][bnn] = bv;
        __syncthreads();
#pragma unroll
        for (int kk = 0; kk < 16; kk++) {
            float4 a4 = *(const float4*)&As[kk][ty * 4];
            float4 b4 = *(const float4*)&Bs[kk][tx * 4];
            float a[4] = {a4.x, a4.y, a4.z, a4.w};
            float bb[4] = {b4.x, b4.y, b4.z, b4.w};
#pragma unroll
            for (int i = 0; i < 4; i++)
#pragma unroll
                for (int j = 0; j < 4; j++) acc[i][j] = fmaf(a[i], bb[j], acc[i][j]);
        }
    }
#pragma unroll
    for (int i = 0; i < 4; i++) {
        int m = ty * 4 + i;
        if (m0 + m < cnt) {
            float4 o;
            o.x = gelu_f(acc[i][0]); o.y = gelu_f(acc[i][1]);
            o.z = gelu_f(acc[i][2]); o.w = gelu_f(acc[i][3]);
            *(float4*)&g_h1[(size_t)toks[m] * R + n0 + tx * 4] = o;
        }
    }
}

// ---------------------------------------------------------------------------
// K3: gathered fused GEMMs + highway epilogue:
//   h2 = h1 @ Wu[e]          (K = R)
//   g  = sigmoid(x @ Wg[e] + bg[e])   (K = H)
//   out = p* * (g*h2 + (1-g)*x)
// ---------------------------------------------------------------------------
__global__ __launch_bounds__(256) void expert_gemm2(
    const float* __restrict__ premise,
    const float* __restrict__ Wu,
    const float* __restrict__ Wg,
    const float* __restrict__ bg,
    float* __restrict__ out) {
    int e = blockIdx.z;
    int cnt = g_counts[e];
    int m0 = blockIdx.y * 64;
    if (m0 >= cnt) return;
    int n0 = blockIdx.x * 64;

    __shared__ float As[16][64];
    __shared__ float Bs[16][64];
    __shared__ int toks[64];

    int tid = threadIdx.x;
    if (tid < 64) toks[tid] = g_tok[e * NTOK + min(m0 + tid, cnt - 1)];
    __syncthreads();

    int tx = tid & 15, ty = tid >> 4;
    int arow = tid >> 2;
    int akk = (tid & 3) * 4;
    int bkk = (tid * 4) >> 6;
    int bnn = (tid * 4) & 63;
    size_t tok_a = (size_t)toks[arow];

    float acc_h[4][4], acc_g[4][4];
#pragma unroll
    for (int i = 0; i < 4; i++)
#pragma unroll
        for (int j = 0; j < 4; j++) { acc_h[i][j] = 0.f; acc_g[i][j] = 0.f; }

    // ---- pass 1: h2 = h1 @ Wu[e], K = R ----
    const float* Wue = Wu + (size_t)e * R * H;
    for (int k0 = 0; k0 < R; k0 += 16) {
        float4 av = *(const float4*)&g_h1[tok_a * R + k0 + akk];
        float4 bv = *(const float4*)&Wue[(size_t)(k0 + bkk) * H + n0 + bnn];
        __syncthreads();
        As[akk + 0][arow] = av.x; As[akk + 1][arow] = av.y;
        As[akk + 2][arow] = av.z; As[akk + 3][arow] = av.w;
        *(float4*)&Bs[bkk][bnn] = bv;
        __syncthreads();
#pragma unroll
        for (int kk = 0; kk < 16; kk++) {
            float4 a4 = *(const float4*)&As[kk][ty * 4];
            float4 b4 = *(const float4*)&Bs[kk][tx * 4];
            float a[4] = {a4.x, a4.y, a4.z, a4.w};
            float bb[4] = {b4.x, b4.y, b4.z, b4.w};
#pragma unroll
            for (int i = 0; i < 4; i++)
#pragma unroll
                for (int j = 0; j < 4; j++) acc_h[i][j] = fmaf(a[i], bb[j], acc_h[i][j]);
        }
    }

    // ---- pass 2: g-logits = x @ Wg[e], K = H ----
    const float* Wge = Wg + (size_t)e * H * H;
    for (int k0 = 0; k0 < H; k0 += 16) {
        float4 av = *(const float4*)&premise[tok_a * H + k0 + akk];
        float4 bv = *(const float4*)&Wge[(size_t)(k0 + bkk) * H + n0 + bnn];
        __syncthreads();
        As[akk + 0][arow] = av.x; As[akk + 1][arow] = av.y;
        As[akk + 2][arow] = av.z; As[akk + 3][arow] = av.w;
        *(float4*)&Bs[bkk][bnn] = bv;
        __syncthreads();
#pragma unroll
        for (int kk = 0; kk < 16; kk++) {
            float4 a4 = *(const float4*)&As[kk][ty * 4];
            float4 b4 = *(const float4*)&Bs[kk][tx * 4];
            float a[4] = {a4.x, a4.y, a4.z, a4.w};
            float bb[4] = {b4.x, b4.y, b4.z, b4.w};
#pragma unroll
            for (int i = 0; i < 4; i++)
#pragma unroll
                for (int j = 0; j < 4; j++) acc_g[i][j] = fmaf(a[i], bb[j], acc_g[i][j]);
        }
    }

    // ---- epilogue ----
    float4 bgv = *(const float4*)&bg[(size_t)e * H + n0 + tx * 4];
    float bga[4] = {bgv.x, bgv.y, bgv.z, bgv.w};
#pragma unroll
    for (int i = 0; i < 4; i++) {
        int m = ty * 4 + i;
        if (m0 + m < cnt) {
            int tok = toks[m];
            float p = g_pstar[tok];
            float4 xv = *(const float4*)&premise[(size_t)tok * H + n0 + tx * 4];
            float x[4] = {xv.x, xv.y, xv.z, xv.w};
            float4 o;
            float* op = &o.x;
#pragma unroll
            for (int j = 0; j < 4; j++) {
                float gg = 1.0f / (1.0f + expf(-(acc_g[i][j] + bga[j])));
                float y = gg * acc_h[i][j] + (1.0f - gg) * x[j];
                op[j] = p * y;
            }
            *(float4*)&out[(size_t)tok * H + n0 + tx * 4] = o;
        }
    }
}

// ---------------------------------------------------------------------------
extern "C" void kernel_launch(void* const* d_in, const int* in_sizes, int n_in,
                              void* d_out, int out_size) {
    const float* premise   = (const float*)d_in[0];
    const float* Wdist     = (const float*)d_in[1];
    const float* bdist     = (const float*)d_in[2];
    const float* centroids = (const float*)d_in[3];
    const float* Wd        = (const float*)d_in[4];
    const float* Wu        = (const float*)d_in[5];
    const float* Wg        = (const float*)d_in[6];
    const float* bg        = (const float*)d_in[7];
    float* out = (float*)d_out;

    prep_kernel<<<1, 256>>>(centroids);
    router_kernel<<<NTOK / 16, 256>>>(premise, Wdist, bdist);
    expert_gemm1<<<dim3(R / 64, NTOK / 64, E), 256>>>(premise, Wd);
    expert_gemm2<<<dim3(H / 64, NTOK / 64, E), 256>>>(premise, Wu, Wg, bg, out);
}

// round 2
// speedup vs baseline: 1.9407x; 1.9407x over previous
#include <cuda_runtime.h>
#include <math.h>

#define NTOK 8192
#define H 2048
#define T 256
#define E 16
#define R 512

// ---- scratch (static __device__, no allocation) ----
__device__ float g_cnorm[E * T];
__device__ int   g_counts[E];
__device__ int   g_tok[E * NTOK];
__device__ float g_pstar[NTOK];
__device__ float g_dist[NTOK * T];
__device__ float g_h1[NTOK * R];

__device__ __forceinline__ float gelu_f(float v) {
    return 0.5f * v * (1.0f + erff(v * 0.70710678118654752440f));
}
__device__ __forceinline__ unsigned f2tf(float x) {
    unsigned u; asm("cvt.rna.tf32.f32 %0, %1;" : "=r"(u) : "f"(x)); return u;
}
__device__ __forceinline__ float4 tf4(float4 v) {
    float4 o;
    o.x = __uint_as_float(f2tf(v.x)); o.y = __uint_as_float(f2tf(v.y));
    o.z = __uint_as_float(f2tf(v.z)); o.w = __uint_as_float(f2tf(v.w));
    return o;
}
__device__ __forceinline__ void mma8(float* c, unsigned a0, unsigned a1, unsigned a2, unsigned a3,
                                     unsigned b0, unsigned b1) {
    asm volatile(
        "mma.sync.aligned.m16n8k8.row.col.f32.tf32.tf32.f32 "
        "{%0,%1,%2,%3}, {%4,%5,%6,%7}, {%8,%9}, {%0,%1,%2,%3};"
        : "+f"(c[0]), "+f"(c[1]), "+f"(c[2]), "+f"(c[3])
        : "r"(a0), "r"(a1), "r"(a2), "r"(a3), "r"(b0), "r"(b1));
}

// ---------------------------------------------------------------------------
// K0: zero counters + normalize centroids
// ---------------------------------------------------------------------------
__global__ void prep_kernel(const float* __restrict__ centroids) {
    __shared__ float inv[E];
    int t = threadIdx.x;
    if (t < E) {
        g_counts[t] = 0;
        float ss = 0.f;
        const float* c = centroids + t * T;
        for (int j = 0; j < T; j++) { float v = c[j]; ss += v * v; }
        inv[t] = 1.0f / fmaxf(sqrtf(ss), 1e-8f);
    }
    __syncthreads();
    for (int idx = t; idx < E * T; idx += blockDim.x)
        g_cnorm[idx] = centroids[idx] * inv[idx / T];
}

// ---------------------------------------------------------------------------
// K1: distill GEMM with 3xTF32 (near-fp32): g_dist = gelu(premise @ Wdist + b)
// Tile 64x64, 128 threads (4 warps as 2x2), K-tile 32.
// ---------------------------------------------------------------------------
__global__ __launch_bounds__(128) void distill_mma(
    const float* __restrict__ premise,
    const float* __restrict__ Wdist,
    const float* __restrict__ bdist) {
    __shared__ float Ah[64][36], Al[64][36];
    __shared__ float Bh[32][72], Bl[32][72];
    int tid = threadIdx.x, lane = tid & 31, warp = tid >> 5;
    int wm = warp >> 1, wn = warp & 1;
    int m0 = blockIdx.y * 64, n0 = blockIdx.x * 64;

    float acc[2][4][4];
#pragma unroll
    for (int i = 0; i < 2; i++)
#pragma unroll
        for (int j = 0; j < 4; j++)
#pragma unroll
            for (int q = 0; q < 4; q++) acc[i][j][q] = 0.f;

    int ar = tid >> 1, ak = (tid & 1) * 16;
    int bk = tid >> 4, bn = (tid & 15) * 4;
    int r = lane >> 2, q = lane & 3;

    for (int k0 = 0; k0 < H; k0 += 32) {
        float4 av[4], bv[4];
#pragma unroll
        for (int i = 0; i < 4; i++)
            av[i] = *(const float4*)&premise[(size_t)(m0 + ar) * H + k0 + ak + 4 * i];
#pragma unroll
        for (int i = 0; i < 4; i++)
            bv[i] = *(const float4*)&Wdist[(size_t)(k0 + bk + 8 * i) * T + n0 + bn];
        __syncthreads();
#pragma unroll
        for (int i = 0; i < 4; i++) {
            const float* p = (const float*)&av[i];
            float4 h4, l4; float* hp = &h4.x; float* lp = &l4.x;
#pragma unroll
            for (int z = 0; z < 4; z++) {
                unsigned hu = f2tf(p[z]); float hf = __uint_as_float(hu);
                hp[z] = hf; lp[z] = __uint_as_float(f2tf(p[z] - hf));
            }
            *(float4*)&Ah[ar][ak + 4 * i] = h4;
            *(float4*)&Al[ar][ak + 4 * i] = l4;
        }
#pragma unroll
        for (int i = 0; i < 4; i++) {
            const float* p = (const float*)&bv[i];
            float4 h4, l4; float* hp = &h4.x; float* lp = &l4.x;
#pragma unroll
            for (int z = 0; z < 4; z++) {
                unsigned hu = f2tf(p[z]); float hf = __uint_as_float(hu);
                hp[z] = hf; lp[z] = __uint_as_float(f2tf(p[z] - hf));
            }
            *(float4*)&Bh[bk + 8 * i][bn] = h4;
            *(float4*)&Bl[bk + 8 * i][bn] = l4;
        }
        __syncthreads();
#pragma unroll
        for (int s = 0; s < 4; s++) {
            unsigned ah[2][4], al2[2][4], bh[4][2], bl2[4][2];
#pragma unroll
            for (int i = 0; i < 2; i++) {
                int row = wm * 32 + i * 16 + r;
                ah[i][0] = __float_as_uint(Ah[row][s * 8 + q]);
                ah[i][1] = __float_as_uint(Ah[row + 8][s * 8 + q]);
                ah[i][2] = __float_as_uint(Ah[row][s * 8 + 4 + q]);
                ah[i][3] = __float_as_uint(Ah[row + 8][s * 8 + 4 + q]);
                al2[i][0] = __float_as_uint(Al[row][s * 8 + q]);
                al2[i][1] = __float_as_uint(Al[row + 8][s * 8 + q]);
                al2[i][2] = __float_as_uint(Al[row][s * 8 + 4 + q]);
                al2[i][3] = __float_as_uint(Al[row + 8][s * 8 + 4 + q]);
            }
#pragma unroll
            for (int j = 0; j < 4; j++) {
                int col = wn * 32 + j * 8 + r;
                bh[j][0] = __float_as_uint(Bh[s * 8 + q][col]);
                bh[j][1] = __float_as_uint(Bh[s * 8 + 4 + q][col]);
                bl2[j][0] = __float_as_uint(Bl[s * 8 + q][col]);
                bl2[j][1] = __float_as_uint(Bl[s * 8 + 4 + q][col]);
            }
#pragma unroll
            for (int i = 0; i < 2; i++)
#pragma unroll
                for (int j = 0; j < 4; j++) {
                    mma8(acc[i][j], ah[i][0], ah[i][1], ah[i][2], ah[i][3], bh[j][0], bh[j][1]);
                    mma8(acc[i][j], ah[i][0], ah[i][1], ah[i][2], ah[i][3], bl2[j][0], bl2[j][1]);
                    mma8(acc[i][j], al2[i][0], al2[i][1], al2[i][2], al2[i][3], bh[j][0], bh[j][1]);
                }
        }
    }
#pragma unroll
    for (int i = 0; i < 2; i++) {
        int row = m0 + wm * 32 + i * 16 + (lane >> 2);
#pragma unroll
        for (int j = 0; j < 4; j++) {
            int col = n0 + wn * 32 + j * 8 + (lane & 3) * 2;
            float b0 = bdist[col], b1 = bdist[col + 1];
            float2 o0, o1;
            o0.x = gelu_f(acc[i][j][0] + b0); o0.y = gelu_f(acc[i][j][1] + b1);
            o1.x = gelu_f(acc[i][j][2] + b0); o1.y = gelu_f(acc[i][j][3] + b1);
            *(float2*)&g_dist[(size_t)row * T + col] = o0;
            *(float2*)&g_dist[(size_t)(row + 8) * T + col] = o1;
        }
    }
}

// ---------------------------------------------------------------------------
// K2: routing decisions from g_dist. One warp per token, 8 tokens per block.
// ---------------------------------------------------------------------------
__global__ __launch_bounds__(256) void route_kernel() {
    __shared__ float cn[E][T];
    int tid = threadIdx.x;
    for (int idx = tid; idx < E * T; idx += 256) cn[idx >> 8][idx & 255] = g_cnorm[idx];
    __syncthreads();
    int warp = tid >> 5, lane = tid & 31;
    int tok = blockIdx.x * 8 + warp;

    float d[8];
#pragma unroll
    for (int i = 0; i < 8; i++) d[i] = g_dist[(size_t)tok * T + lane + 32 * i];
    float ss = 0.f;
#pragma unroll
    for (int i = 0; i < 8; i++) ss += d[i] * d[i];
#pragma unroll
    for (int o = 16; o; o >>= 1) ss += __shfl_xor_sync(0xffffffffu, ss, o);
    float inv = 1.0f / fmaxf(sqrtf(ss), 1e-8f);

    float mydot = 0.f;
#pragma unroll
    for (int ee = 0; ee < E; ee++) {
        float p = 0.f;
#pragma unroll
        for (int i = 0; i < 8; i++) p = fmaf(d[i], cn[ee][lane + 32 * i], p);
#pragma unroll
        for (int o = 16; o; o >>= 1) p += __shfl_xor_sync(0xffffffffu, p, o);
        if (lane == ee) mydot = p;
    }
    float logit = -1e30f;
    if (lane < E) {
        float dot = mydot * inv;
        float dist = sqrtf(fmaxf(2.f - 2.f * dot, 0.f));
        logit = -dist;
    }
    float mx = logit;
#pragma unroll
    for (int o = 16; o; o >>= 1) mx = fmaxf(mx, __shfl_xor_sync(0xffffffffu, mx, o));
    float ex = (lane < E) ? expf(logit - mx) : 0.f;
    float sum = ex;
#pragma unroll
    for (int o = 16; o; o >>= 1) sum += __shfl_xor_sync(0xffffffffu, sum, o);
    float prob = ex / sum;

    float p1 = prob; int i1 = lane;
#pragma unroll
    for (int o = 16; o; o >>= 1) {
        float po = __shfl_xor_sync(0xffffffffu, p1, o);
        int   io = __shfl_xor_sync(0xffffffffu, i1, o);
        if (po > p1 || (po == p1 && io < i1)) { p1 = po; i1 = io; }
    }
    float p2 = (lane == i1) ? -1.f : prob; int i2 = lane;
#pragma unroll
    for (int o = 16; o; o >>= 1) {
        float po = __shfl_xor_sync(0xffffffffu, p2, o);
        int   io = __shfl_xor_sync(0xffffffffu, i2, o);
        if (po > p2 || (po == p2 && io < i2)) { p2 = po; i2 = io; }
    }
    int e_star = max(i1, i2);
    float p_star = (e_star == i1) ? p1 : p2;
    if (lane == 0) {
        g_pstar[tok] = p_star;
        int pos = atomicAdd(&g_counts[e_star], 1);
        g_tok[e_star * NTOK + pos] = tok;
    }
}

// ---------------------------------------------------------------------------
// Shared tile-compute helper: 128x64 block tile, 256 threads (8 warps 4x2),
// K-tile 32, 1xTF32.
// ---------------------------------------------------------------------------
__device__ __forceinline__ void compute_ktile(
    float acc[2][4][4], const float (*As)[36], const float (*Bs)[72],
    int wm, int wn, int lane) {
    int r = lane >> 2, q = lane & 3;
#pragma unroll
    for (int s = 0; s < 4; s++) {
        unsigned a[2][4], b[4][2];
#pragma unroll
        for (int i = 0; i < 2; i++) {
            int row = wm * 32 + i * 16 + r;
            a[i][0] = __float_as_uint(As[row][s * 8 + q]);
            a[i][1] = __float_as_uint(As[row + 8][s * 8 + q]);
            a[i][2] = __float_as_uint(As[row][s * 8 + 4 + q]);
            a[i][3] = __float_as_uint(As[row + 8][s * 8 + 4 + q]);
        }
#pragma unroll
        for (int j = 0; j < 4; j++) {
            int col = wn * 32 + j * 8 + r;
            b[j][0] = __float_as_uint(Bs[s * 8 + q][col]);
            b[j][1] = __float_as_uint(Bs[s * 8 + 4 + q][col]);
        }
#pragma unroll
        for (int i = 0; i < 2; i++)
#pragma unroll
            for (int j = 0; j < 4; j++)
                mma8(acc[i][j], a[i][0], a[i][1], a[i][2], a[i][3], b[j][0], b[j][1]);
    }
}

// ---------------------------------------------------------------------------
// K3: gathered GEMM  h1 = gelu(X_e @ Wd[e])
// ---------------------------------------------------------------------------
__global__ __launch_bounds__(256) void expert_gemm1(
    const float* __restrict__ premise, const float* __restrict__ Wd) {
    int e = blockIdx.z;
    int cnt = g_counts[e];
    __shared__ float As[128][36];
    __shared__ float Bs[32][72];
    __shared__ int toks[128];
    int tid = threadIdx.x, lane = tid & 31, warp = tid >> 5;
    int wm = warp >> 1, wn = warp & 1;
    const float* Wde = Wd + (size_t)e * H * R;
    int n0 = blockIdx.x * 64;
    int ar = tid >> 1, ak = (tid & 1) * 16;
    int bk = tid >> 3, bn = (tid & 7) * 8;

    for (int m0 = blockIdx.y * 128; m0 < cnt; m0 += gridDim.y * 128) {
        __syncthreads();
        if (tid < 128) toks[tid] = g_tok[e * NTOK + min(m0 + tid, cnt - 1)];
        __syncthreads();
        size_t abase = (size_t)toks[ar] * H;
        float acc[2][4][4];
#pragma unroll
        for (int i = 0; i < 2; i++)
#pragma unroll
            for (int j = 0; j < 4; j++)
#pragma unroll
                for (int z = 0; z < 4; z++) acc[i][j][z] = 0.f;

        for (int k0 = 0; k0 < H; k0 += 32) {
            float4 av[4], bv0, bv1;
#pragma unroll
            for (int i = 0; i < 4; i++)
                av[i] = *(const float4*)&premise[abase + k0 + ak + 4 * i];
            bv0 = *(const float4*)&Wde[(size_t)(k0 + bk) * R + n0 + bn];
            bv1 = *(const float4*)&Wde[(size_t)(k0 + bk) * R + n0 + bn + 4];
            __syncthreads();
#pragma unroll
            for (int i = 0; i < 4; i++) *(float4*)&As[ar][ak + 4 * i] = tf4(av[i]);
            *(float4*)&Bs[bk][bn] = tf4(bv0);
            *(float4*)&Bs[bk][bn + 4] = tf4(bv1);
            __syncthreads();
            compute_ktile(acc, As, Bs, wm, wn, lane);
        }
#pragma unroll
        for (int i = 0; i < 2; i++) {
            int rl0 = wm * 32 + i * 16 + (lane >> 2);
#pragma unroll
            for (int j = 0; j < 4; j++) {
                int col = n0 + wn * 32 + j * 8 + (lane & 3) * 2;
                if (m0 + rl0 < cnt) {
                    float2 o; o.x = gelu_f(acc[i][j][0]); o.y = gelu_f(acc[i][j][1]);
                    *(float2*)&g_h1[(size_t)toks[rl0] * R + col] = o;
                }
                if (m0 + rl0 + 8 < cnt) {
                    float2 o; o.x = gelu_f(acc[i][j][2]); o.y = gelu_f(acc[i][j][3]);
                    *(float2*)&g_h1[(size_t)toks[rl0 + 8] * R + col] = o;
                }
            }
        }
    }
}

// ---------------------------------------------------------------------------
// K4: gathered fused GEMMs + highway epilogue
// ---------------------------------------------------------------------------
__global__ __launch_bounds__(256) void expert_gemm2(
    const float* __restrict__ premise,
    const float* __restrict__ Wu,
    const float* __restrict__ Wg,
    const float* __restrict__ bg,
    float* __restrict__ out) {
    int e = blockIdx.z;
    int cnt = g_counts[e];
    __shared__ float As[128][36];
    __shared__ float Bs[32][72];
    __shared__ int toks[128];
    int tid = threadIdx.x, lane = tid & 31, warp = tid >> 5;
    int wm = warp >> 1, wn = warp & 1;
    const float* Wue = Wu + (size_t)e * R * H;
    const float* Wge = Wg + (size_t)e * H * H;
    int n0 = blockIdx.x * 64;
    int ar = tid >> 1, ak = (tid & 1) * 16;
    int bk = tid >> 3, bn = (tid & 7) * 8;

    for (int m0 = blockIdx.y * 128; m0 < cnt; m0 += gridDim.y * 128) {
        __syncthreads();
        if (tid < 128) toks[tid] = g_tok[e * NTOK + min(m0 + tid, cnt - 1)];
        __syncthreads();
        size_t tokA = (size_t)toks[ar];
        float accH[2][4][4], accG[2][4][4];
#pragma unroll
        for (int i = 0; i < 2; i++)
#pragma unroll
            for (int j = 0; j < 4; j++)
#pragma unroll
                for (int z = 0; z < 4; z++) { accH[i][j][z] = 0.f; accG[i][j][z] = 0.f; }

        // pass 1: h2 = h1 @ Wu[e], K = R
        for (int k0 = 0; k0 < R; k0 += 32) {
            float4 av[4], bv0, bv1;
#pragma unroll
            for (int i = 0; i < 4; i++)
                av[i] = *(const float4*)&g_h1[tokA * R + k0 + ak + 4 * i];
            bv0 = *(const float4*)&Wue[(size_t)(k0 + bk) * H + n0 + bn];
            bv1 = *(const float4*)&Wue[(size_t)(k0 + bk) * H + n0 + bn + 4];
            __syncthreads();
#pragma unroll
            for (int i = 0; i < 4; i++) *(float4*)&As[ar][ak + 4 * i] = tf4(av[i]);
            *(float4*)&Bs[bk][bn] = tf4(bv0);
            *(float4*)&Bs[bk][bn + 4] = tf4(bv1);
            __syncthreads();
            compute_ktile(accH, As, Bs, wm, wn, lane);
        }
        // pass 2: g-logits = x @ Wg[e], K = H
        for (int k0 = 0; k0 < H; k0 += 32) {
            float4 av[4], bv0, bv1;
#pragma unroll
            for (int i = 0; i < 4; i++)
                av[i] = *(const float4*)&premise[tokA * H + k0 + ak + 4 * i];
            bv0 = *(const float4*)&Wge[(size_t)(k0 + bk) * H + n0 + bn];
            bv1 = *(const float4*)&Wge[(size_t)(k0 + bk) * H + n0 + bn + 4];
            __syncthreads();
#pragma unroll
            for (int i = 0; i < 4; i++) *(float4*)&As[ar][ak + 4 * i] = tf4(av[i]);
            *(float4*)&Bs[bk][bn] = tf4(bv0);
            *(float4*)&Bs[bk][bn + 4] = tf4(bv1);
            __syncthreads();
            compute_ktile(accG, As, Bs, wm, wn, lane);
        }
        // epilogue
#pragma unroll
        for (int i = 0; i < 2; i++) {
            int rl0 = wm * 32 + i * 16 + (lane >> 2);
#pragma unroll
            for (int half = 0; half < 2; half++) {
                int rl = rl0 + half * 8;
                if (m0 + rl < cnt) {
                    int tok = toks[rl];
                    float p = g_pstar[tok];
#pragma unroll
                    for (int j = 0; j < 4; j++) {
                        int col = n0 + wn * 32 + j * 8 + (lane & 3) * 2;
                        float bg0 = bg[(size_t)e * H + col];
                        float bg1 = bg[(size_t)e * H + col + 1];
                        float2 xv = *(const float2*)&premise[(size_t)tok * H + col];
                        float h0 = accH[i][j][half * 2], h1v = accH[i][j][half * 2 + 1];
                        float z0 = accG[i][j][half * 2] + bg0, z1 = accG[i][j][half * 2 + 1] + bg1;
                        float gg0 = 1.0f / (1.0f + expf(-z0));
                        float gg1 = 1.0f / (1.0f + expf(-z1));
                        float2 o;
                        o.x = p * (gg0 * h0 + (1.0f - gg0) * xv.x);
                        o.y = p * (gg1 * h1v + (1.0f - gg1) * xv.y);
                        *(float2*)&out[(size_t)tok * H + col] = o;
                    }
                }
            }
        }
    }
}

// ---------------------------------------------------------------------------
extern "C" void kernel_launch(void* const* d_in, const int* in_sizes, int n_in,
                              void* d_out, int out_size) {
    const float* premise   = (const float*)d_in[0];
    const float* Wdist     = (const float*)d_in[1];
    const float* bdist     = (const float*)d_in[2];
    const float* centroids = (const float*)d_in[3];
    const float* Wd        = (const float*)d_in[4];
    const float* Wu        = (const float*)d_in[5];
    const float* Wg        = (const float*)d_in[6];
    const float* bg        = (const float*)d_in[7];
    float* out = (float*)d_out;

    prep_kernel<<<1, 256>>>(centroids);
    distill_mma<<<dim3(T / 64, NTOK / 64), 128>>>(premise, Wdist, bdist);
    route_kernel<<<NTOK / 8, 256>>>();
    expert_gemm1<<<dim3(R / 64, 4, E), 256>>>(premise, Wd);
    expert_gemm2<<<dim3(H / 64, 4, E), 256>>>(premise, Wu, Wg, bg, out);
}

// round 4
// speedup vs baseline: 2.5590x; 1.3186x over previous
#include <cuda_runtime.h>
#include <math.h>

#define NTOK 8192
#define H 2048
#define T 256
#define E 16
#define R 512

#define BM 128
#define BN 64
#define BK 16
#define STG 3

// ---- scratch ----
__device__ float g_cnorm[E * T];
__device__ int   g_counts[E];
__device__ int   g_tok[E * NTOK];
__device__ float g_pstar[NTOK];
__device__ float g_dist[NTOK * T];
__device__ float g_h1[NTOK * R];

__device__ __forceinline__ float gelu_f(float v) {
    return 0.5f * v * (1.0f + erff(v * 0.70710678118654752440f));
}
__device__ __forceinline__ unsigned f2tf(float x) {
    unsigned u; asm("cvt.rna.tf32.f32 %0, %1;" : "=r"(u) : "f"(x)); return u;
}
__device__ __forceinline__ void mma8(float* c, unsigned a0, unsigned a1, unsigned a2, unsigned a3,
                                     unsigned b0, unsigned b1) {
    asm volatile(
        "mma.sync.aligned.m16n8k8.row.col.f32.tf32.tf32.f32 "
        "{%0,%1,%2,%3}, {%4,%5,%6,%7}, {%8,%9}, {%0,%1,%2,%3};"
        : "+f"(c[0]), "+f"(c[1]), "+f"(c[2]), "+f"(c[3])
        : "r"(a0), "r"(a1), "r"(a2), "r"(a3), "r"(b0), "r"(b1));
}
__device__ __forceinline__ void cpa16(void* s, const void* g) {
    unsigned sa = (unsigned)__cvta_generic_to_shared(s);
    asm volatile("cp.async.cg.shared.global [%0], [%1], 16;" :: "r"(sa), "l"(g) : "memory");
}
#define CP_COMMIT() asm volatile("cp.async.commit_group;" ::: "memory")
#define CP_WAIT(n)  asm volatile("cp.async.wait_group %0;" :: "n"(n) : "memory")

// 1xTF32 fragment compute on one BK=16 tile (convert at frag load, RNA)
__device__ __forceinline__ void compute_ktile16(
    float acc[2][4][4], const float (*A)[BK + 4], const float (*B)[BN + 8],
    int wm, int wn, int lane) {
    int r = lane >> 2, q = lane & 3;
#pragma unroll
    for (int s = 0; s < 2; s++) {
        unsigned a[2][4], b[4][2];
#pragma unroll
        for (int i = 0; i < 2; i++) {
            int row = wm * 32 + i * 16 + r;
            a[i][0] = f2tf(A[row][s * 8 + q]);
            a[i][1] = f2tf(A[row + 8][s * 8 + q]);
            a[i][2] = f2tf(A[row][s * 8 + 4 + q]);
            a[i][3] = f2tf(A[row + 8][s * 8 + 4 + q]);
        }
#pragma unroll
        for (int j = 0; j < 4; j++) {
            int col = wn * 32 + j * 8 + r;
            b[j][0] = f2tf(B[s * 8 + q][col]);
            b[j][1] = f2tf(B[s * 8 + 4 + q][col]);
        }
#pragma unroll
        for (int i = 0; i < 2; i++)
#pragma unroll
            for (int j = 0; j < 4; j++)
                mma8(acc[i][j], a[i][0], a[i][1], a[i][2], a[i][3], b[j][0], b[j][1]);
    }
}

// ---------------------------------------------------------------------------
// K0: zero counters + normalize centroids
// ---------------------------------------------------------------------------
__global__ void prep_kernel(const float* __restrict__ centroids) {
    __shared__ float inv[E];
    int t = threadIdx.x;
    if (t < E) {
        g_counts[t] = 0;
        float ss = 0.f;
        const float* c = centroids + t * T;
        for (int j = 0; j < T; j++) { float v = c[j]; ss += v * v; }
        inv[t] = 1.0f / fmaxf(sqrtf(ss), 1e-8f);
    }
    __syncthreads();
    for (int idx = t; idx < E * T; idx += blockDim.x)
        g_cnorm[idx] = centroids[idx] * inv[idx / T];
}

// ---------------------------------------------------------------------------
// K1: distill GEMM, 3xTF32 compensated, cp.async 3-stage pipeline.
// 128x64 tile, 256 threads (8 warps 4x2).
// ---------------------------------------------------------------------------
__global__ __launch_bounds__(256) void distill_mma(
    const float* __restrict__ premise,
    const float* __restrict__ Wdist,
    const float* __restrict__ bdist) {
    __shared__ float As[STG][BM][BK + 4];
    __shared__ float Bs[STG][BK][BN + 8];
    int tid = threadIdx.x, lane = tid & 31, warp = tid >> 5;
    int wm = warp >> 1, wn = warp & 1;
    int m0 = blockIdx.y * BM, n0 = blockIdx.x * BN;
    int arow = tid >> 2, akc = (tid & 3) * 4;
    int bkr = tid >> 4, bnc = (tid & 15) * 4;
    size_t rowA0 = (size_t)(m0 + arow) * H;
    size_t rowA1 = (size_t)(m0 + arow + 64) * H;

    float acc[2][4][4];
#pragma unroll
    for (int i = 0; i < 2; i++)
#pragma unroll
        for (int j = 0; j < 4; j++)
#pragma unroll
            for (int z = 0; z < 4; z++) acc[i][j][z] = 0.f;

    const int NT = H / BK;
#pragma unroll
    for (int s = 0; s < STG - 1; s++) {
        int k0 = s * BK;
        cpa16(&As[s][arow][akc], &premise[rowA0 + k0 + akc]);
        cpa16(&As[s][arow + 64][akc], &premise[rowA1 + k0 + akc]);
        cpa16(&Bs[s][bkr][bnc], &Wdist[(size_t)(k0 + bkr) * T + n0 + bnc]);
        CP_COMMIT();
    }
    for (int it = 0; it < NT; it++) {
        CP_WAIT(STG - 2);
        __syncthreads();
        int ld = it + STG - 1;
        if (ld < NT) {
            int st = ld % STG; int k0 = ld * BK;
            cpa16(&As[st][arow][akc], &premise[rowA0 + k0 + akc]);
            cpa16(&As[st][arow + 64][akc], &premise[rowA1 + k0 + akc]);
            cpa16(&Bs[st][bkr][bnc], &Wdist[(size_t)(k0 + bkr) * T + n0 + bnc]);
        }
        CP_COMMIT();
        const float (*A)[BK + 4] = As[it % STG];
        const float (*B)[BN + 8] = Bs[it % STG];
        int r = lane >> 2, q = lane & 3;
#pragma unroll
        for (int s = 0; s < 2; s++) {
            unsigned ah[2][4], al[2][4], bh[4][2], bl[4][2];
#pragma unroll
            for (int i = 0; i < 2; i++) {
                int row = wm * 32 + i * 16 + r;
                float x0 = A[row][s * 8 + q], x1 = A[row + 8][s * 8 + q];
                float x2 = A[row][s * 8 + 4 + q], x3 = A[row + 8][s * 8 + 4 + q];
                ah[i][0] = f2tf(x0); al[i][0] = f2tf(x0 - __uint_as_float(ah[i][0]));
                ah[i][1] = f2tf(x1); al[i][1] = f2tf(x1 - __uint_as_float(ah[i][1]));
                ah[i][2] = f2tf(x2); al[i][2] = f2tf(x2 - __uint_as_float(ah[i][2]));
                ah[i][3] = f2tf(x3); al[i][3] = f2tf(x3 - __uint_as_float(ah[i][3]));
            }
#pragma unroll
            for (int j = 0; j < 4; j++) {
                int col = wn * 32 + j * 8 + r;
                float y0 = B[s * 8 + q][col], y1 = B[s * 8 + 4 + q][col];
                bh[j][0] = f2tf(y0); bl[j][0] = f2tf(y0 - __uint_as_float(bh[j][0]));
                bh[j][1] = f2tf(y1); bl[j][1] = f2tf(y1 - __uint_as_float(bh[j][1]));
            }
#pragma unroll
            for (int i = 0; i < 2; i++)
#pragma unroll
                for (int j = 0; j < 4; j++) {
                    mma8(acc[i][j], ah[i][0], ah[i][1], ah[i][2], ah[i][3], bh[j][0], bh[j][1]);
                    mma8(acc[i][j], ah[i][0], ah[i][1], ah[i][2], ah[i][3], bl[j][0], bl[j][1]);
                    mma8(acc[i][j], al[i][0], al[i][1], al[i][2], al[i][3], bh[j][0], bh[j][1]);
                }
        }
    }
#pragma unroll
    for (int i = 0; i < 2; i++) {
        int row = m0 + wm * 32 + i * 16 + (lane >> 2);
#pragma unroll
        for (int j = 0; j < 4; j++) {
            int col = n0 + wn * 32 + j * 8 + (lane & 3) * 2;
            float b0 = bdist[col], b1 = bdist[col + 1];
            float2 o0, o1;
            o0.x = gelu_f(acc[i][j][0] + b0); o0.y = gelu_f(acc[i][j][1] + b1);
            o1.x = gelu_f(acc[i][j][2] + b0); o1.y = gelu_f(acc[i][j][3] + b1);
            *(float2*)&g_dist[(size_t)row * T + col] = o0;
            *(float2*)&g_dist[(size_t)(row + 8) * T + col] = o1;
        }
    }
}

// ---------------------------------------------------------------------------
// K2: routing decisions. One warp per token.
// ---------------------------------------------------------------------------
__global__ __launch_bounds__(256) void route_kernel() {
    __shared__ float cn[E][T];
    int tid = threadIdx.x;
    for (int idx = tid; idx < E * T; idx += 256) cn[idx >> 8][idx & 255] = g_cnorm[idx];
    __syncthreads();
    int warp = tid >> 5, lane = tid & 31;
    int tok = blockIdx.x * 8 + warp;

    float d[8];
#pragma unroll
    for (int i = 0; i < 8; i++) d[i] = g_dist[(size_t)tok * T + lane + 32 * i];
    float ss = 0.f;
#pragma unroll
    for (int i = 0; i < 8; i++) ss += d[i] * d[i];
#pragma unroll
    for (int o = 16; o; o >>= 1) ss += __shfl_xor_sync(0xffffffffu, ss, o);
    float inv = 1.0f / fmaxf(sqrtf(ss), 1e-8f);

    float mydot = 0.f;
#pragma unroll
    for (int ee = 0; ee < E; ee++) {
        float p = 0.f;
#pragma unroll
        for (int i = 0; i < 8; i++) p = fmaf(d[i], cn[ee][lane + 32 * i], p);
#pragma unroll
        for (int o = 16; o; o >>= 1) p += __shfl_xor_sync(0xffffffffu, p, o);
        if (lane == ee) mydot = p;
    }
    float logit = -1e30f;
    if (lane < E) {
        float dot = mydot * inv;
        float dist = sqrtf(fmaxf(2.f - 2.f * dot, 0.f));
        logit = -dist;
    }
    float mx = logit;
#pragma unroll
    for (int o = 16; o; o >>= 1) mx = fmaxf(mx, __shfl_xor_sync(0xffffffffu, mx, o));
    float ex = (lane < E) ? expf(logit - mx) : 0.f;
    float sum = ex;
#pragma unroll
    for (int o = 16; o; o >>= 1) sum += __shfl_xor_sync(0xffffffffu, sum, o);
    float prob = ex / sum;

    float p1 = prob; int i1 = lane;
#pragma unroll
    for (int o = 16; o; o >>= 1) {
        float po = __shfl_xor_sync(0xffffffffu, p1, o);
        int   io = __shfl_xor_sync(0xffffffffu, i1, o);
        if (po > p1 || (po == p1 && io < i1)) { p1 = po; i1 = io; }
    }
    float p2 = (lane == i1) ? -1.f : prob; int i2 = lane;
#pragma unroll
    for (int o = 16; o; o >>= 1) {
        float po = __shfl_xor_sync(0xffffffffu, p2, o);
        int   io = __shfl_xor_sync(0xffffffffu, i2, o);
        if (po > p2 || (po == p2 && io < i2)) { p2 = po; i2 = io; }
    }
    int e_star = max(i1, i2);
    float p_star = (e_star == i1) ? p1 : p2;
    if (lane == 0) {
        g_pstar[tok] = p_star;
        int pos = atomicAdd(&g_counts[e_star], 1);
        g_tok[e_star * NTOK + pos] = tok;
    }
}

// ---------------------------------------------------------------------------
// K3: gathered GEMM h1 = gelu(X_e @ Wd[e]), pipelined.
// ---------------------------------------------------------------------------
__global__ __launch_bounds__(256) void expert_gemm1(
    const float* __restrict__ premise, const float* __restrict__ Wd) {
    int e = blockIdx.z;
    int cnt = g_counts[e];
    __shared__ float As[STG][BM][BK + 4];
    __shared__ float Bs[STG][BK][BN + 8];
    __shared__ int toks[BM];
    int tid = threadIdx.x, lane = tid & 31, warp = tid >> 5;
    int wm = warp >> 1, wn = warp & 1;
    const float* Wde = Wd + (size_t)e * H * R;
    int n0 = blockIdx.x * BN;
    int arow = tid >> 2, akc = (tid & 3) * 4;
    int bkr = tid >> 4, bnc = (tid & 15) * 4;

    for (int m0 = blockIdx.y * BM; m0 < cnt; m0 += gridDim.y * BM) {
        __syncthreads();
        if (tid < BM) toks[tid] = g_tok[e * NTOK + min(m0 + tid, cnt - 1)];
        __syncthreads();
        size_t rowA0 = (size_t)toks[arow] * H;
        size_t rowA1 = (size_t)toks[arow + 64] * H;
        float acc[2][4][4];
#pragma unroll
        for (int i = 0; i < 2; i++)
#pragma unroll
            for (int j = 0; j < 4; j++)
#pragma unroll
                for (int z = 0; z < 4; z++) acc[i][j][z] = 0.f;

        const int NT = H / BK;
#pragma unroll
        for (int s = 0; s < STG - 1; s++) {
            int k0 = s * BK;
            cpa16(&As[s][arow][akc], &premise[rowA0 + k0 + akc]);
            cpa16(&As[s][arow + 64][akc], &premise[rowA1 + k0 + akc]);
            cpa16(&Bs[s][bkr][bnc], &Wde[(size_t)(k0 + bkr) * R + n0 + bnc]);
            CP_COMMIT();
        }
        for (int it = 0; it < NT; it++) {
            CP_WAIT(STG - 2);
            __syncthreads();
            int ld = it + STG - 1;
            if (ld < NT) {
                int st = ld % STG; int k0 = ld * BK;
                cpa16(&As[st][arow][akc], &premise[rowA0 + k0 + akc]);
                cpa16(&As[st][arow + 64][akc], &premise[rowA1 + k0 + akc]);
                cpa16(&Bs[st][bkr][bnc], &Wde[(size_t)(k0 + bkr) * R + n0 + bnc]);
            }
            CP_COMMIT();
            compute_ktile16(acc, As[it % STG], Bs[it % STG], wm, wn, lane);
        }
#pragma unroll
        for (int i = 0; i < 2; i++) {
            int rl0 = wm * 32 + i * 16 + (lane >> 2);
#pragma unroll
            for (int j = 0; j < 4; j++) {
                int col = n0 + wn * 32 + j * 8 + (lane & 3) * 2;
                if (m0 + rl0 < cnt) {
                    float2 o; o.x = gelu_f(acc[i][j][0]); o.y = gelu_f(acc[i][j][1]);
                    *(float2*)&g_h1[(size_t)toks[rl0] * R + col] = o;
                }
                if (m0 + rl0 + 8 < cnt) {
                    float2 o; o.x = gelu_f(acc[i][j][2]); o.y = gelu_f(acc[i][j][3]);
                    *(float2*)&g_h1[(size_t)toks[rl0 + 8] * R + col] = o;
                }
            }
        }
    }
}

// ---------------------------------------------------------------------------
// K4: gathered fused GEMMs + highway epilogue, pipelined both passes.
// ---------------------------------------------------------------------------
__global__ __launch_bounds__(256) void expert_gemm2(
    const float* __restrict__ premise,
    const float* __restrict__ Wu,
    const float* __restrict__ Wg,
    const float* __restrict__ bg,
    float* __restrict__ out) {
    int e = blockIdx.z;
    int cnt = g_counts[e];
    __shared__ float As[STG][BM][BK + 4];
    __shared__ float Bs[STG][BK][BN + 8];
    __shared__ int toks[BM];
    int tid = threadIdx.x, lane = tid & 31, warp = tid >> 5;
    int wm = warp >> 1, wn = warp & 1;
    const float* Wue = Wu + (size_t)e * R * H;
    const float* Wge = Wg + (size_t)e * H * H;
    int n0 = blockIdx.x * BN;
    int arow = tid >> 2, akc = (tid & 3) * 4;
    int bkr = tid >> 4, bnc = (tid & 15) * 4;

    for (int m0 = blockIdx.y * BM; m0 < cnt; m0 += gridDim.y * BM) {
        __syncthreads();
        if (tid < BM) toks[tid] = g_tok[e * NTOK + min(m0 + tid, cnt - 1)];
        __syncthreads();
        size_t tokA0 = (size_t)toks[arow];
        size_t tokA1 = (size_t)toks[arow + 64];
        float accH[2][4][4], accG[2][4][4];
#pragma unroll
        for (int i = 0; i < 2; i++)
#pragma unroll
            for (int j = 0; j < 4; j++)
#pragma unroll
                for (int z = 0; z < 4; z++) { accH[i][j][z] = 0.f; accG[i][j][z] = 0.f; }

        // ---- pass 1: h2 = h1 @ Wu[e], K = R ----
        {
            const int NT = R / BK;
#pragma unroll
            for (int s = 0; s < STG - 1; s++) {
                int k0 = s * BK;
                cpa16(&As[s][arow][akc], &g_h1[tokA0 * R + k0 + akc]);
                cpa16(&As[s][arow + 64][akc], &g_h1[tokA1 * R + k0 + akc]);
                cpa16(&Bs[s][bkr][bnc], &Wue[(size_t)(k0 + bkr) * H + n0 + bnc]);
                CP_COMMIT();
            }
            for (int it = 0; it < NT; it++) {
                CP_WAIT(STG - 2);
                __syncthreads();
                int ld = it + STG - 1;
                if (ld < NT) {
                    int st = ld % STG; int k0 = ld * BK;
                    cpa16(&As[st][arow][akc], &g_h1[tokA0 * R + k0 + akc]);
                    cpa16(&As[st][arow + 64][akc], &g_h1[tokA1 * R + k0 + akc]);
                    cpa16(&Bs[st][bkr][bnc], &Wue[(size_t)(k0 + bkr) * H + n0 + bnc]);
                }
                CP_COMMIT();
                compute_ktile16(accH, As[it % STG], Bs[it % STG], wm, wn, lane);
            }
        }
        __syncthreads();
        // ---- pass 2: g-logits = x @ Wg[e], K = H ----
        {
            const int NT = H / BK;
#pragma unroll
            for (int s = 0; s < STG - 1; s++) {
                int k0 = s * BK;
                cpa16(&As[s][arow][akc], &premise[tokA0 * H + k0 + akc]);
                cpa16(&As[s][arow + 64][akc], &premise[tokA1 * H + k0 + akc]);
                cpa16(&Bs[s][bkr][bnc], &Wge[(size_t)(k0 + bkr) * H + n0 + bnc]);
                CP_COMMIT();
            }
            for (int it = 0; it < NT; it++) {
                CP_WAIT(STG - 2);
                __syncthreads();
                int ld = it + STG - 1;
                if (ld < NT) {
                    int st = ld % STG; int k0 = ld * BK;
                    cpa16(&As[st][arow][akc], &premise[tokA0 * H + k0 + akc]);
                    cpa16(&As[st][arow + 64][akc], &premise[tokA1 * H + k0 + akc]);
                    cpa16(&Bs[st][bkr][bnc], &Wge[(size_t)(k0 + bkr) * H + n0 + bnc]);
                }
                CP_COMMIT();
                compute_ktile16(accG, As[it % STG], Bs[it % STG], wm, wn, lane);
            }
        }
        // ---- epilogue ----
#pragma unroll
        for (int i = 0; i < 2; i++) {
            int rl0 = wm * 32 + i * 16 + (lane >> 2);
#pragma unroll
            for (int half = 0; half < 2; half++) {
                int rl = rl0 + half * 8;
                if (m0 + rl < cnt) {
                    int tok = toks[rl];
                    float p = g_pstar[tok];
#pragma unroll
                    for (int j = 0; j < 4; j++) {
                        int col = n0 + wn * 32 + j * 8 + (lane & 3) * 2;
                        float bg0 = bg[(size_t)e * H + col];
                        float bg1 = bg[(size_t)e * H + col + 1];
                        float2 xv = *(const float2*)&premise[(size_t)tok * H + col];
                        float h0 = accH[i][j][half * 2], h1v = accH[i][j][half * 2 + 1];
                        float z0 = accG[i][j][half * 2] + bg0, z1 = accG[i][j][half * 2 + 1] + bg1;
                        float gg0 = 1.0f / (1.0f + expf(-z0));
                        float gg1 = 1.0f / (1.0f + expf(-z1));
                        float2 o;
                        o.x = p * (gg0 * h0 + (1.0f - gg0) * xv.x);
                        o.y = p * (gg1 * h1v + (1.0f - gg1) * xv.y);
                        *(float2*)&out[(size_t)tok * H + col] = o;
                    }
                }
            }
        }
    }
}

// ---------------------------------------------------------------------------
extern "C" void kernel_launch(void* const* d_in, const int* in_sizes, int n_in,
                              void* d_out, int out_size) {
    const float* premise   = (const float*)d_in[0];
    const float* Wdist     = (const float*)d_in[1];
    const float* bdist     = (const float*)d_in[2];
    const float* centroids = (const float*)d_in[3];
    const float* Wd        = (const float*)d_in[4];
    const float* Wu        = (const float*)d_in[5];
    const float* Wg        = (const float*)d_in[6];
    const float* bg        = (const float*)d_in[7];
    float* out = (float*)d_out;

    prep_kernel<<<1, 256>>>(centroids);
    distill_mma<<<dim3(T / BN, NTOK / BM), 256>>>(premise, Wdist, bdist);
    route_kernel<<<NTOK / 8, 256>>>();
    expert_gemm1<<<dim3(R / BN, 4, E), 256>>>(premise, Wd);
    expert_gemm2<<<dim3(H / BN, 4, E), 256>>>(premise, Wu, Wg, bg, out);
}

// round 5
// speedup vs baseline: 2.6966x; 1.0538x over previous
#include <cuda_runtime.h>
#include <math.h>

#define NTOK 8192
#define H 2048
#define T 256
#define E 16
#define R 512

#define BM 128
#define BK 16
#define STG 3

// ---- scratch ----
__device__ float g_cnorm[E * T];
__device__ int   g_counts[E];
__device__ int   g_tok[E * NTOK];
__device__ float g_pstar[NTOK];
__device__ float g_dist[NTOK * T];
__device__ float g_h1[NTOK * R];
__device__ float g_ph[NTOK * H];   // premise tf32-hi
__device__ float g_pl[NTOK * H];   // premise tf32-lo
__device__ float g_wh[H * T];      // Wdist tf32-hi
__device__ float g_wl[H * T];      // Wdist tf32-lo

__device__ __forceinline__ float gelu_f(float v) {
    return 0.5f * v * (1.0f + erff(v * 0.70710678118654752440f));
}
__device__ __forceinline__ unsigned f2tf(float x) {
    unsigned u; asm("cvt.rna.tf32.f32 %0, %1;" : "=r"(u) : "f"(x)); return u;
}
__device__ __forceinline__ void mma8(float* c, unsigned a0, unsigned a1, unsigned a2, unsigned a3,
                                     unsigned b0, unsigned b1) {
    asm volatile(
        "mma.sync.aligned.m16n8k8.row.col.f32.tf32.tf32.f32 "
        "{%0,%1,%2,%3}, {%4,%5,%6,%7}, {%8,%9}, {%0,%1,%2,%3};"
        : "+f"(c[0]), "+f"(c[1]), "+f"(c[2]), "+f"(c[3])
        : "r"(a0), "r"(a1), "r"(a2), "r"(a3), "r"(b0), "r"(b1));
}
__device__ __forceinline__ void cpa16(void* s, const void* g) {
    unsigned sa = (unsigned)__cvta_generic_to_shared(s);
    asm volatile("cp.async.cg.shared.global [%0], [%1], 16;" :: "r"(sa), "l"(g) : "memory");
}
#define CP_COMMIT() asm volatile("cp.async.commit_group;" ::: "memory")
#define CP_WAIT(n)  asm volatile("cp.async.wait_group %0;" :: "n"(n) : "memory")

// ---------------------------------------------------------------------------
// K0a: zero counters + normalize centroids
// ---------------------------------------------------------------------------
__global__ void prep_kernel(const float* __restrict__ centroids) {
    __shared__ float inv[E];
    int t = threadIdx.x;
    if (t < E) {
        g_counts[t] = 0;
        float ss = 0.f;
        const float* c = centroids + t * T;
        for (int j = 0; j < T; j++) { float v = c[j]; ss += v * v; }
        inv[t] = 1.0f / fmaxf(sqrtf(ss), 1e-8f);
    }
    __syncthreads();
    for (int idx = t; idx < E * T; idx += blockDim.x)
        g_cnorm[idx] = centroids[idx] * inv[idx / T];
}

// ---------------------------------------------------------------------------
// K0b: tf32 hi/lo split of premise and Wdist (for 3xTF32 distill)
// ---------------------------------------------------------------------------
__global__ __launch_bounds__(256) void split_kernel(
    const float* __restrict__ premise, const float* __restrict__ Wdist) {
    size_t i = (size_t)blockIdx.x * 256 + threadIdx.x;
    size_t np = (size_t)NTOK * H / 4;
    size_t nw = (size_t)H * T / 4;
    if (i < np) {
        float4 v = ((const float4*)premise)[i];
        float4 h, l;
        h.x = __uint_as_float(f2tf(v.x)); l.x = __uint_as_float(f2tf(v.x - h.x));
        h.y = __uint_as_float(f2tf(v.y)); l.y = __uint_as_float(f2tf(v.y - h.y));
        h.z = __uint_as_float(f2tf(v.z)); l.z = __uint_as_float(f2tf(v.z - h.z));
        h.w = __uint_as_float(f2tf(v.w)); l.w = __uint_as_float(f2tf(v.w - h.w));
        ((float4*)g_ph)[i] = h; ((float4*)g_pl)[i] = l;
    }
    if (i < nw) {
        float4 v = ((const float4*)Wdist)[i];
        float4 h, l;
        h.x = __uint_as_float(f2tf(v.x)); l.x = __uint_as_float(f2tf(v.x - h.x));
        h.y = __uint_as_float(f2tf(v.y)); l.y = __uint_as_float(f2tf(v.y - h.y));
        h.z = __uint_as_float(f2tf(v.z)); l.z = __uint_as_float(f2tf(v.z - h.z));
        h.w = __uint_as_float(f2tf(v.w)); l.w = __uint_as_float(f2tf(v.w - h.w));
        ((float4*)g_wh)[i] = h; ((float4*)g_wl)[i] = l;
    }
}

// ---------------------------------------------------------------------------
// K1: distill GEMM, 3xTF32 from pre-split hi/lo, cp.async pipeline.
// 128x64 tile, 256 threads (8 warps 4x2, warp tile 32x32).
// ---------------------------------------------------------------------------
__global__ __launch_bounds__(256) void distill_mma(const float* __restrict__ bdist) {
    __shared__ float Ah[STG][BM][BK + 4], Al[STG][BM][BK + 4];
    __shared__ float Bh[STG][BK][64 + 8], Bl[STG][BK][64 + 8];
    int tid = threadIdx.x, lane = tid & 31, warp = tid >> 5;
    int wm = warp >> 1, wn = warp & 1;
    int m0 = blockIdx.y * BM, n0 = blockIdx.x * 64;
    int arow = tid >> 2, akc = (tid & 3) * 4;
    int bkr = tid >> 4, bnc = (tid & 15) * 4;
    size_t rowA0 = (size_t)(m0 + arow) * H;
    size_t rowA1 = (size_t)(m0 + arow + 64) * H;

    float acc[2][4][4];
#pragma unroll
    for (int i = 0; i < 2; i++)
#pragma unroll
        for (int j = 0; j < 4; j++)
#pragma unroll
            for (int z = 0; z < 4; z++) acc[i][j][z] = 0.f;

    const int NT = H / BK;
#pragma unroll
    for (int s = 0; s < STG - 1; s++) {
        int k0 = s * BK;
        cpa16(&Ah[s][arow][akc], &g_ph[rowA0 + k0 + akc]);
        cpa16(&Ah[s][arow + 64][akc], &g_ph[rowA1 + k0 + akc]);
        cpa16(&Al[s][arow][akc], &g_pl[rowA0 + k0 + akc]);
        cpa16(&Al[s][arow + 64][akc], &g_pl[rowA1 + k0 + akc]);
        cpa16(&Bh[s][bkr][bnc], &g_wh[(size_t)(k0 + bkr) * T + n0 + bnc]);
        cpa16(&Bl[s][bkr][bnc], &g_wl[(size_t)(k0 + bkr) * T + n0 + bnc]);
        CP_COMMIT();
    }
    for (int it = 0; it < NT; it++) {
        CP_WAIT(STG - 2);
        __syncthreads();
        int ld = it + STG - 1;
        if (ld < NT) {
            int st = ld % STG; int k0 = ld * BK;
            cpa16(&Ah[st][arow][akc], &g_ph[rowA0 + k0 + akc]);
            cpa16(&Ah[st][arow + 64][akc], &g_ph[rowA1 + k0 + akc]);
            cpa16(&Al[st][arow][akc], &g_pl[rowA0 + k0 + akc]);
            cpa16(&Al[st][arow + 64][akc], &g_pl[rowA1 + k0 + akc]);
            cpa16(&Bh[st][bkr][bnc], &g_wh[(size_t)(k0 + bkr) * T + n0 + bnc]);
            cpa16(&Bl[st][bkr][bnc], &g_wl[(size_t)(k0 + bkr) * T + n0 + bnc]);
        }
        CP_COMMIT();
        int buf = it % STG;
        int r = lane >> 2, q = lane & 3;
#pragma unroll
        for (int s = 0; s < 2; s++) {
            unsigned ah[2][4], al[2][4], bh[4][2], bl[4][2];
#pragma unroll
            for (int i = 0; i < 2; i++) {
                int row = wm * 32 + i * 16 + r;
                ah[i][0] = __float_as_uint(Ah[buf][row][s * 8 + q]);
                ah[i][1] = __float_as_uint(Ah[buf][row + 8][s * 8 + q]);
                ah[i][2] = __float_as_uint(Ah[buf][row][s * 8 + 4 + q]);
                ah[i][3] = __float_as_uint(Ah[buf][row + 8][s * 8 + 4 + q]);
                al[i][0] = __float_as_uint(Al[buf][row][s * 8 + q]);
                al[i][1] = __float_as_uint(Al[buf][row + 8][s * 8 + q]);
                al[i][2] = __float_as_uint(Al[buf][row][s * 8 + 4 + q]);
                al[i][3] = __float_as_uint(Al[buf][row + 8][s * 8 + 4 + q]);
            }
#pragma unroll
            for (int j = 0; j < 4; j++) {
                int col = wn * 32 + j * 8 + r;
                bh[j][0] = __float_as_uint(Bh[buf][s * 8 + q][col]);
                bh[j][1] = __float_as_uint(Bh[buf][s * 8 + 4 + q][col]);
                bl[j][0] = __float_as_uint(Bl[buf][s * 8 + q][col]);
                bl[j][1] = __float_as_uint(Bl[buf][s * 8 + 4 + q][col]);
            }
#pragma unroll
            for (int i = 0; i < 2; i++)
#pragma unroll
                for (int j = 0; j < 4; j++) {
                    mma8(acc[i][j], ah[i][0], ah[i][1], ah[i][2], ah[i][3], bh[j][0], bh[j][1]);
                    mma8(acc[i][j], ah[i][0], ah[i][1], ah[i][2], ah[i][3], bl[j][0], bl[j][1]);
                    mma8(acc[i][j], al[i][0], al[i][1], al[i][2], al[i][3], bh[j][0], bh[j][1]);
                }
        }
    }
#pragma unroll
    for (int i = 0; i < 2; i++) {
        int row = m0 + wm * 32 + i * 16 + (lane >> 2);
#pragma unroll
        for (int j = 0; j < 4; j++) {
            int col = n0 + wn * 32 + j * 8 + (lane & 3) * 2;
            float b0 = bdist[col], b1 = bdist[col + 1];
            float2 o0, o1;
            o0.x = gelu_f(acc[i][j][0] + b0); o0.y = gelu_f(acc[i][j][1] + b1);
            o1.x = gelu_f(acc[i][j][2] + b0); o1.y = gelu_f(acc[i][j][3] + b1);
            *(float2*)&g_dist[(size_t)row * T + col] = o0;
            *(float2*)&g_dist[(size_t)(row + 8) * T + col] = o1;
        }
    }
}

// ---------------------------------------------------------------------------
// K2: routing decisions. One warp per token.
// ---------------------------------------------------------------------------
__global__ __launch_bounds__(256) void route_kernel() {
    __shared__ float cn[E][T];
    int tid = threadIdx.x;
    for (int idx = tid; idx < E * T; idx += 256) cn[idx >> 8][idx & 255] = g_cnorm[idx];
    __syncthreads();
    int warp = tid >> 5, lane = tid & 31;
    int tok = blockIdx.x * 8 + warp;

    float d[8];
#pragma unroll
    for (int i = 0; i < 8; i++) d[i] = g_dist[(size_t)tok * T + lane + 32 * i];
    float ss = 0.f;
#pragma unroll
    for (int i = 0; i < 8; i++) ss += d[i] * d[i];
#pragma unroll
    for (int o = 16; o; o >>= 1) ss += __shfl_xor_sync(0xffffffffu, ss, o);
    float inv = 1.0f / fmaxf(sqrtf(ss), 1e-8f);

    float mydot = 0.f;
#pragma unroll
    for (int ee = 0; ee < E; ee++) {
        float p = 0.f;
#pragma unroll
        for (int i = 0; i < 8; i++) p = fmaf(d[i], cn[ee][lane + 32 * i], p);
#pragma unroll
        for (int o = 16; o; o >>= 1) p += __shfl_xor_sync(0xffffffffu, p, o);
        if (lane == ee) mydot = p;
    }
    float logit = -1e30f;
    if (lane < E) {
        float dot = mydot * inv;
        float dist = sqrtf(fmaxf(2.f - 2.f * dot, 0.f));
        logit = -dist;
    }
    float mx = logit;
#pragma unroll
    for (int o = 16; o; o >>= 1) mx = fmaxf(mx, __shfl_xor_sync(0xffffffffu, mx, o));
    float ex = (lane < E) ? expf(logit - mx) : 0.f;
    float sum = ex;
#pragma unroll
    for (int o = 16; o; o >>= 1) sum += __shfl_xor_sync(0xffffffffu, sum, o);
    float prob = ex / sum;

    float p1 = prob; int i1 = lane;
#pragma unroll
    for (int o = 16; o; o >>= 1) {
        float po = __shfl_xor_sync(0xffffffffu, p1, o);
        int   io = __shfl_xor_sync(0xffffffffu, i1, o);
        if (po > p1 || (po == p1 && io < i1)) { p1 = po; i1 = io; }
    }
    float p2 = (lane == i1) ? -1.f : prob; int i2 = lane;
#pragma unroll
    for (int o = 16; o; o >>= 1) {
        float po = __shfl_xor_sync(0xffffffffu, p2, o);
        int   io = __shfl_xor_sync(0xffffffffu, i2, o);
        if (po > p2 || (po == p2 && io < i2)) { p2 = po; i2 = io; }
    }
    int e_star = max(i1, i2);
    float p_star = (e_star == i1) ? p1 : p2;
    if (lane == 0) {
        g_pstar[tok] = p_star;
        int pos = atomicAdd(&g_counts[e_star], 1);
        g_tok[e_star * NTOK + pos] = tok;
    }
}

// ---------------------------------------------------------------------------
// K3: gathered GEMM h1 = gelu(X_e @ Wd[e]). 128x128 tile, warp tile 32x64.
// No cvt: raw fp32 regs fed to tf32 HMMA (HW ignores low mantissa bits).
// ---------------------------------------------------------------------------
__global__ __launch_bounds__(256) void expert_gemm1(
    const float* __restrict__ premise, const float* __restrict__ Wd) {
    int e = blockIdx.z;
    int cnt = g_counts[e];
    __shared__ float As[STG][BM][BK + 4];
    __shared__ float Bs[STG][BK][128 + 8];
    __shared__ int toks[BM];
    int tid = threadIdx.x, lane = tid & 31, warp = tid >> 5;
    int wm = warp >> 1, wn = warp & 1;
    const float* Wde = Wd + (size_t)e * H * R;
    int n0 = blockIdx.x * 128;
    int arow = tid >> 2, akc = (tid & 3) * 4;
    int bkr = tid >> 4, bnc = (tid & 15) * 8;

    for (int m0 = blockIdx.y * BM; m0 < cnt; m0 += gridDim.y * BM) {
        __syncthreads();
        if (tid < BM) toks[tid] = g_tok[e * NTOK + min(m0 + tid, cnt - 1)];
        __syncthreads();
        size_t rowA0 = (size_t)toks[arow] * H;
        size_t rowA1 = (size_t)toks[arow + 64] * H;
        float acc[2][8][4];
#pragma unroll
        for (int i = 0; i < 2; i++)
#pragma unroll
            for (int j = 0; j < 8; j++)
#pragma unroll
                for (int z = 0; z < 4; z++) acc[i][j][z] = 0.f;

        const int NT = H / BK;
#pragma unroll
        for (int s = 0; s < STG - 1; s++) {
            int k0 = s * BK;
            cpa16(&As[s][arow][akc], &premise[rowA0 + k0 + akc]);
            cpa16(&As[s][arow + 64][akc], &premise[rowA1 + k0 + akc]);
            cpa16(&Bs[s][bkr][bnc], &Wde[(size_t)(k0 + bkr) * R + n0 + bnc]);
            cpa16(&Bs[s][bkr][bnc + 4], &Wde[(size_t)(k0 + bkr) * R + n0 + bnc + 4]);
            CP_COMMIT();
        }
        for (int it = 0; it < NT; it++) {
            CP_WAIT(STG - 2);
            __syncthreads();
            int ld = it + STG - 1;
            if (ld < NT) {
                int st = ld % STG; int k0 = ld * BK;
                cpa16(&As[st][arow][akc], &premise[rowA0 + k0 + akc]);
                cpa16(&As[st][arow + 64][akc], &premise[rowA1 + k0 + akc]);
                cpa16(&Bs[st][bkr][bnc], &Wde[(size_t)(k0 + bkr) * R + n0 + bnc]);
                cpa16(&Bs[st][bkr][bnc + 4], &Wde[(size_t)(k0 + bkr) * R + n0 + bnc + 4]);
            }
            CP_COMMIT();
            int buf = it % STG;
            int r = lane >> 2, q = lane & 3;
#pragma unroll
            for (int s = 0; s < 2; s++) {
                unsigned a[2][4], b[8][2];
#pragma unroll
                for (int i = 0; i < 2; i++) {
                    int row = wm * 32 + i * 16 + r;
                    a[i][0] = __float_as_uint(As[buf][row][s * 8 + q]);
                    a[i][1] = __float_as_uint(As[buf][row + 8][s * 8 + q]);
                    a[i][2] = __float_as_uint(As[buf][row][s * 8 + 4 + q]);
                    a[i][3] = __float_as_uint(As[buf][row + 8][s * 8 + 4 + q]);
                }
#pragma unroll
                for (int j = 0; j < 8; j++) {
                    int col = wn * 64 + j * 8 + r;
                    b[j][0] = __float_as_uint(Bs[buf][s * 8 + q][col]);
                    b[j][1] = __float_as_uint(Bs[buf][s * 8 + 4 + q][col]);
                }
#pragma unroll
                for (int i = 0; i < 2; i++)
#pragma unroll
                    for (int j = 0; j < 8; j++)
                        mma8(acc[i][j], a[i][0], a[i][1], a[i][2], a[i][3], b[j][0], b[j][1]);
            }
        }
#pragma unroll
        for (int i = 0; i < 2; i++) {
            int rl0 = wm * 32 + i * 16 + (lane >> 2);
#pragma unroll
            for (int j = 0; j < 8; j++) {
                int col = n0 + wn * 64 + j * 8 + (lane & 3) * 2;
                if (m0 + rl0 < cnt) {
                    float2 o; o.x = gelu_f(acc[i][j][0]); o.y = gelu_f(acc[i][j][1]);
                    *(float2*)&g_h1[(size_t)toks[rl0] * R + col] = o;
                }
                if (m0 + rl0 + 8 < cnt) {
                    float2 o; o.x = gelu_f(acc[i][j][2]); o.y = gelu_f(acc[i][j][3]);
                    *(float2*)&g_h1[(size_t)toks[rl0 + 8] * R + col] = o;
                }
            }
        }
    }
}

// ---------------------------------------------------------------------------
// K4: gathered fused GEMMs + highway epilogue. 128x64, no cvt.
// ---------------------------------------------------------------------------
__device__ __forceinline__ void compute_ktile_raw(
    float acc[2][4][4], const float (*A)[BK + 4], const float (*B)[64 + 8],
    int wm, int wn, int lane) {
    int r = lane >> 2, q = lane & 3;
#pragma unroll
    for (int s = 0; s < 2; s++) {
        unsigned a[2][4], b[4][2];
#pragma unroll
        for (int i = 0; i < 2; i++) {
            int row = wm * 32 + i * 16 + r;
            a[i][0] = __float_as_uint(A[row][s * 8 + q]);
            a[i][1] = __float_as_uint(A[row + 8][s * 8 + q]);
            a[i][2] = __float_as_uint(A[row][s * 8 + 4 + q]);
            a[i][3] = __float_as_uint(A[row + 8][s * 8 + 4 + q]);
        }
#pragma unroll
        for (int j = 0; j < 4; j++) {
            int col = wn * 32 + j * 8 + r;
            b[j][0] = __float_as_uint(B[s * 8 + q][col]);
            b[j][1] = __float_as_uint(B[s * 8 + 4 + q][col]);
        }
#pragma unroll
        for (int i = 0; i < 2; i++)
#pragma unroll
            for (int j = 0; j < 4; j++)
                mma8(acc[i][j], a[i][0], a[i][1], a[i][2], a[i][3], b[j][0], b[j][1]);
    }
}

__global__ __launch_bounds__(256) void expert_gemm2(
    const float* __restrict__ premise,
    const float* __restrict__ Wu,
    const float* __restrict__ Wg,
    const float* __restrict__ bg,
    float* __restrict__ out) {
    int e = blockIdx.z;
    int cnt = g_counts[e];
    __shared__ float As[STG][BM][BK + 4];
    __shared__ float Bs[STG][BK][64 + 8];
    __shared__ int toks[BM];
    int tid = threadIdx.x, lane = tid & 31, warp = tid >> 5;
    int wm = warp >> 1, wn = warp & 1;
    const float* Wue = Wu + (size_t)e * R * H;
    const float* Wge = Wg + (size_t)e * H * H;
    int n0 = blockIdx.x * 64;
    int arow = tid >> 2, akc = (tid & 3) * 4;
    int bkr = tid >> 4, bnc = (tid & 15) * 4;

    for (int m0 = blockIdx.y * BM; m0 < cnt; m0 += gridDim.y * BM) {
        __syncthreads();
        if (tid < BM) toks[tid] = g_tok[e * NTOK + min(m0 + tid, cnt - 1)];
        __syncthreads();
        size_t tokA0 = (size_t)toks[arow];
        size_t tokA1 = (size_t)toks[arow + 64];
        float accH[2][4][4], accG[2][4][4];
#pragma unroll
        for (int i = 0; i < 2; i++)
#pragma unroll
            for (int j = 0; j < 4; j++)
#pragma unroll
                for (int z = 0; z < 4; z++) { accH[i][j][z] = 0.f; accG[i][j][z] = 0.f; }

        // ---- pass 1: h2 = h1 @ Wu[e], K = R ----
        {
            const int NT = R / BK;
#pragma unroll
            for (int s = 0; s < STG - 1; s++) {
                int k0 = s * BK;
                cpa16(&As[s][arow][akc], &g_h1[tokA0 * R + k0 + akc]);
                cpa16(&As[s][arow + 64][akc], &g_h1[tokA1 * R + k0 + akc]);
                cpa16(&Bs[s][bkr][bnc], &Wue[(size_t)(k0 + bkr) * H + n0 + bnc]);
                CP_COMMIT();
            }
            for (int it = 0; it < NT; it++) {
                CP_WAIT(STG - 2);
                __syncthreads();
                int ld = it + STG - 1;
                if (ld < NT) {
                    int st = ld % STG; int k0 = ld * BK;
                    cpa16(&As[st][arow][akc], &g_h1[tokA0 * R + k0 + akc]);
                    cpa16(&As[st][arow + 64][akc], &g_h1[tokA1 * R + k0 + akc]);
                    cpa16(&Bs[st][bkr][bnc], &Wue[(size_t)(k0 + bkr) * H + n0 + bnc]);
                }
                CP_COMMIT();
                compute_ktile_raw(accH, As[it % STG], Bs[it % STG], wm, wn, lane);
            }
        }
        __syncthreads();
        // ---- pass 2: g-logits = x @ Wg[e], K = H ----
        {
            const int NT = H / BK;
#pragma unroll
            for (int s = 0; s < STG - 1; s++) {
                int k0 = s * BK;
                cpa16(&As[s][arow][akc], &premise[tokA0 * H + k0 + akc]);
                cpa16(&As[s][arow + 64][akc], &premise[tokA1 * H + k0 + akc]);
                cpa16(&Bs[s][bkr][bnc], &Wge[(size_t)(k0 + bkr) * H + n0 + bnc]);
                CP_COMMIT();
            }
            for (int it = 0; it < NT; it++) {
                CP_WAIT(STG - 2);
                __syncthreads();
                int ld = it + STG - 1;
                if (ld < NT) {
                    int st = ld % STG; int k0 = ld * BK;
                    cpa16(&As[st][arow][akc], &premise[tokA0 * H + k0 + akc]);
                    cpa16(&As[st][arow + 64][akc], &premise[tokA1 * H + k0 + akc]);
                    cpa16(&Bs[st][bkr][bnc], &Wge[(size_t)(k0 + bkr) * H + n0 + bnc]);
                }
                CP_COMMIT();
                compute_ktile_raw(accG, As[it % STG], Bs[it % STG], wm, wn, lane);
            }
        }
        // ---- epilogue ----
#pragma unroll
        for (int i = 0; i < 2; i++) {
            int rl0 = wm * 32 + i * 16 + (lane >> 2);
#pragma unroll
            for (int half = 0; half < 2; half++) {
                int rl = rl0 + half * 8;
                if (m0 + rl < cnt) {
                    int tok = toks[rl];
                    float p = g_pstar[tok];
#pragma unroll
                    for (int j = 0; j < 4; j++) {
                        int col = n0 + wn * 32 + j * 8 + (lane & 3) * 2;
                        float bg0 = bg[(size_t)e * H + col];
                        float bg1 = bg[(size_t)e * H + col + 1];
                        float2 xv = *(const float2*)&premise[(size_t)tok * H + col];
                        float h0 = accH[i][j][half * 2], h1v = accH[i][j][half * 2 + 1];
                        float z0 = accG[i][j][half * 2] + bg0, z1 = accG[i][j][half * 2 + 1] + bg1;
                        float gg0 = 1.0f / (1.0f + expf(-z0));
                        float gg1 = 1.0f / (1.0f + expf(-z1));
                        float2 o;
                        o.x = p * (gg0 * h0 + (1.0f - gg0) * xv.x);
                        o.y = p * (gg1 * h1v + (1.0f - gg1) * xv.y);
                        *(float2*)&out[(size_t)tok * H + col] = o;
                    }
                }
            }
        }
    }
}

// ---------------------------------------------------------------------------
extern "C" void kernel_launch(void* const* d_in, const int* in_sizes, int n_in,
                              void* d_out, int out_size) {
    const float* premise   = (const float*)d_in[0];
    const float* Wdist     = (const float*)d_in[1];
    const float* bdist     = (const float*)d_in[2];
    const float* centroids = (const float*)d_in[3];
    const float* Wd        = (const float*)d_in[4];
    const float* Wu        = (const float*)d_in[5];
    const float* Wg        = (const float*)d_in[6];
    const float* bg        = (const float*)d_in[7];
    float* out = (float*)d_out;

    prep_kernel<<<1, 256>>>(centroids);
    split_kernel<<<(NTOK * H / 4 + 255) / 256, 256>>>(premise, Wdist);
    distill_mma<<<dim3(T / 64, NTOK / BM), 256>>>(bdist);
    route_kernel<<<NTOK / 8, 256>>>();
    expert_gemm1<<<dim3(R / 128, 4, E), 256>>>(premise, Wd);
    expert_gemm2<<<dim3(H / 64, 4, E), 256>>>(premise, Wu, Wg, bg, out);
}